// round 1
// baseline (speedup 1.0000x reference)
#include <cuda_runtime.h>
#include <stdint.h>

#define NH   12
#define SQ   1024
#define NB   8
#define HID  768
#define MROWS (NB*SQ)   // 8192

// Scratch (allocation-free rule: device globals)
__device__ float g_q[MROWS*HID];
__device__ float g_k[MROWS*HID];
__device__ float g_v[MROWS*HID];
__device__ float g_attn[MROWS*HID];

// ---------------------------------------------------------------------------
// GEMM: out[m][n] = sum_k X[m][k] * W[n][k] + bias[n]
// M=8192, N=768, K=768. Block tile 64x64, K-tile 16, 256 threads, 4x4/thread.
// ---------------------------------------------------------------------------
__device__ __forceinline__ void gemm768(const float* __restrict__ X,
                                        const float* __restrict__ W,
                                        const float* __restrict__ bias,
                                        float* __restrict__ out)
{
    __shared__ __align__(16) float As[16][68];
    __shared__ __align__(16) float Bs[16][68];

    const int tid = threadIdx.x;
    const int m0 = blockIdx.x * 64;
    const int n0 = blockIdx.y * 64;
    const int lr = tid >> 2;    // 0..63 (row for loads)
    const int lc = tid & 3;     // 0..3  (k-segment for loads)
    const int tx = tid & 15;    // output col group
    const int ty = tid >> 4;    // output row group

    float acc[4][4];
#pragma unroll
    for (int i = 0; i < 4; i++)
#pragma unroll
        for (int j = 0; j < 4; j++) acc[i][j] = 0.f;

    const float* xp = X + (m0 + lr) * HID + lc * 4;
    const float* wp = W + (n0 + lr) * HID + lc * 4;

    for (int k0 = 0; k0 < HID; k0 += 16) {
        float4 a = *(const float4*)(xp + k0);
        float4 w = *(const float4*)(wp + k0);
        As[lc*4+0][lr] = a.x; As[lc*4+1][lr] = a.y;
        As[lc*4+2][lr] = a.z; As[lc*4+3][lr] = a.w;
        Bs[lc*4+0][lr] = w.x; Bs[lc*4+1][lr] = w.y;
        Bs[lc*4+2][lr] = w.z; Bs[lc*4+3][lr] = w.w;
        __syncthreads();
#pragma unroll
        for (int kk = 0; kk < 16; kk++) {
            float4 av = *(const float4*)&As[kk][ty*4];
            float4 bv = *(const float4*)&Bs[kk][tx*4];
            float ar[4] = {av.x, av.y, av.z, av.w};
            float br[4] = {bv.x, bv.y, bv.z, bv.w};
#pragma unroll
            for (int i = 0; i < 4; i++)
#pragma unroll
                for (int j = 0; j < 4; j++)
                    acc[i][j] += ar[i] * br[j];
        }
        __syncthreads();
    }

    const int nc = n0 + tx * 4;
    float4 bb = *(const float4*)(bias + nc);
#pragma unroll
    for (int i = 0; i < 4; i++) {
        float4 o;
        o.x = acc[i][0] + bb.x;
        o.y = acc[i][1] + bb.y;
        o.z = acc[i][2] + bb.z;
        o.w = acc[i][3] + bb.w;
        *(float4*)(out + (m0 + ty*4 + i) * HID + nc) = o;
    }
}

__global__ void __launch_bounds__(256) qkv_kernel(const float* __restrict__ X,
    const float* __restrict__ Wq, const float* __restrict__ bq,
    const float* __restrict__ Wk, const float* __restrict__ bk,
    const float* __restrict__ Wv, const float* __restrict__ bv)
{
    const float* W; const float* b; float* out;
    if (blockIdx.z == 0)      { W = Wq; b = bq; out = g_q; }
    else if (blockIdx.z == 1) { W = Wk; b = bk; out = g_k; }
    else                      { W = Wv; b = bv; out = g_v; }
    gemm768(X, W, b, out);
}

__global__ void __launch_bounds__(256) oproj_kernel(const float* __restrict__ Wo,
                                                    const float* __restrict__ bo,
                                                    float* __restrict__ out)
{
    gemm768(g_attn, Wo, bo, out);
}

// ---------------------------------------------------------------------------
// Flash attention with additive bias (sp_enc + edge_enc) and boolean mask.
// One block = (batch b, head h, 64 query rows). 16 key tiles of 64.
// Thread layout: r = tid/4 (query row), quad = tid%4 owning 16 cols.
// 48KB static smem: Qs, Kt (reused for P), Vs — 4 CTAs/SM.
// ---------------------------------------------------------------------------
__global__ void __launch_bounds__(256) attn_kernel(const float* __restrict__ sp,
                                                   const float* __restrict__ ed,
                                                   const unsigned char* __restrict__ mk)
{
    __shared__ __align__(16) float Qs[64*64];
    __shared__ __align__(16) float Kt[64*64];   // K transposed; reused as P
    __shared__ __align__(16) float Vs[64*64];

    const int tid = threadIdx.x;
    const int b  = blockIdx.y / NH;
    const int h  = blockIdx.y % NH;
    const int q0 = blockIdx.x * 64;
    const int lr = tid >> 2;    // 0..63
    const int ls = tid & 3;     // 0..3

    // Load Q tile, pre-scaled by 1/sqrt(64) = 0.125
    {
        const float4* src = (const float4*)(g_q + (b*SQ + q0 + lr)*HID + h*64 + ls*16);
        float4* dst = (float4*)(Qs + lr*64 + ls*16);
#pragma unroll
        for (int i = 0; i < 4; i++) {
            float4 t = src[i];
            t.x *= 0.125f; t.y *= 0.125f; t.z *= 0.125f; t.w *= 0.125f;
            dst[i] = t;
        }
    }

    const int r  = lr;
    const int c0 = ls * 16;
    float m_i = -1e30f, l_i = 0.f;
    float acc[16];
#pragma unroll
    for (int j = 0; j < 16; j++) acc[j] = 0.f;

    const size_t biasRow = (size_t)b * SQ * SQ + (size_t)(q0 + r) * SQ;

    for (int kt = 0; kt < 16; kt++) {
        const int k0 = kt * 64;
        __syncthreads();   // protect Kt/Vs from previous iteration (and Qs store)

        // Load K (transposed into Kt[d][c]) and V (row-major Vs[c][d])
        {
            const float4* ks = (const float4*)(g_k + (b*SQ + k0 + lr)*HID + h*64 + ls*16);
#pragma unroll
            for (int i = 0; i < 4; i++) {
                float4 t = ks[i];
                int d = ls*16 + i*4;
                Kt[(d+0)*64 + lr] = t.x;
                Kt[(d+1)*64 + lr] = t.y;
                Kt[(d+2)*64 + lr] = t.z;
                Kt[(d+3)*64 + lr] = t.w;
            }
            const float4* vs = (const float4*)(g_v + (b*SQ + k0 + lr)*HID + h*64 + ls*16);
            float4* vd = (float4*)(Vs + lr*64 + ls*16);
#pragma unroll
            for (int i = 0; i < 4; i++) vd[i] = vs[i];
        }
        __syncthreads();

        // scores = bias + Q.Kt
        float sv[16];
        {
            const float4* spr = (const float4*)(sp + biasRow + k0 + c0);
            const float4* edr = (const float4*)(ed + biasRow + k0 + c0);
#pragma unroll
            for (int jj = 0; jj < 4; jj++) {
                float4 s4 = spr[jj];
                float4 e4 = edr[jj];
                sv[jj*4+0] = s4.x + e4.x;
                sv[jj*4+1] = s4.y + e4.y;
                sv[jj*4+2] = s4.z + e4.z;
                sv[jj*4+3] = s4.w + e4.w;
            }
        }
#pragma unroll 8
        for (int d = 0; d < 64; d++) {
            float qv = Qs[r*64 + d];
            const float4* kk = (const float4*)(Kt + d*64 + c0);
#pragma unroll
            for (int jj = 0; jj < 4; jj++) {
                float4 kv = kk[jj];
                sv[jj*4+0] += qv * kv.x;
                sv[jj*4+1] += qv * kv.y;
                sv[jj*4+2] += qv * kv.z;
                sv[jj*4+3] += qv * kv.w;
            }
        }
        // mask
        {
            uint4 mv = *(const uint4*)(mk + biasRow + k0 + c0);
            unsigned int mw[4] = {mv.x, mv.y, mv.z, mv.w};
#pragma unroll
            for (int jj = 0; jj < 4; jj++)
#pragma unroll
                for (int bi = 0; bi < 4; bi++)
                    if ((mw[jj] >> (8*bi)) & 0xffu) sv[jj*4+bi] = -1e30f;
        }

        // online softmax update (4 lanes per row cooperate via shfl)
        float mx = sv[0];
#pragma unroll
        for (int j = 1; j < 16; j++) mx = fmaxf(mx, sv[j]);
        mx = fmaxf(mx, __shfl_xor_sync(0xffffffffu, mx, 1));
        mx = fmaxf(mx, __shfl_xor_sync(0xffffffffu, mx, 2));
        const float m_new = fmaxf(m_i, mx);
        const float alpha = __expf(m_i - m_new);
        float psum = 0.f;
#pragma unroll
        for (int j = 0; j < 16; j++) { sv[j] = __expf(sv[j] - m_new); psum += sv[j]; }
        psum += __shfl_xor_sync(0xffffffffu, psum, 1);
        psum += __shfl_xor_sync(0xffffffffu, psum, 2);
        l_i = l_i * alpha + psum;
        m_i = m_new;
#pragma unroll
        for (int j = 0; j < 16; j++) acc[j] *= alpha;

        __syncthreads();   // done reading Kt as K
        // write P into Kt buffer
        {
            float4* pd = (float4*)(Kt + r*64 + c0);
#pragma unroll
            for (int jj = 0; jj < 4; jj++)
                pd[jj] = make_float4(sv[jj*4+0], sv[jj*4+1], sv[jj*4+2], sv[jj*4+3]);
        }
        __syncthreads();

        // acc += P @ V   (thread owns d-cols [c0, c0+16))
#pragma unroll 8
        for (int c = 0; c < 64; c++) {
            float p = Kt[r*64 + c];
            const float4* vv = (const float4*)(Vs + c*64 + c0);
#pragma unroll
            for (int jj = 0; jj < 4; jj++) {
                float4 v = vv[jj];
                acc[jj*4+0] += p * v.x;
                acc[jj*4+1] += p * v.y;
                acc[jj*4+2] += p * v.z;
                acc[jj*4+3] += p * v.w;
            }
        }
    }

    const float inv = 1.f / l_i;
    float4* op = (float4*)(g_attn + (b*SQ + q0 + r)*HID + h*64 + c0);
#pragma unroll
    for (int jj = 0; jj < 4; jj++)
        op[jj] = make_float4(acc[jj*4+0]*inv, acc[jj*4+1]*inv,
                             acc[jj*4+2]*inv, acc[jj*4+3]*inv);
}

// ---------------------------------------------------------------------------
extern "C" void kernel_launch(void* const* d_in, const int* in_sizes, int n_in,
                              void* d_out, int out_size)
{
    const float* x  = (const float*)d_in[0];
    const float* sp = (const float*)d_in[1];
    const float* ed = (const float*)d_in[2];
    const unsigned char* mk = (const unsigned char*)d_in[3];
    const float* Wq = (const float*)d_in[4];
    const float* bq = (const float*)d_in[5];
    const float* Wk = (const float*)d_in[6];
    const float* bk = (const float*)d_in[7];
    const float* Wv = (const float*)d_in[8];
    const float* bv = (const float*)d_in[9];
    const float* Wo = (const float*)d_in[10];
    const float* bo = (const float*)d_in[11];
    float* out = (float*)d_out;

    dim3 gq(MROWS/64, HID/64, 3);      // 128 x 12 x 3
    qkv_kernel<<<gq, 256>>>(x, Wq, bq, Wk, bk, Wv, bv);

    dim3 ga(SQ/64, NB*NH);             // 16 x 96
    attn_kernel<<<ga, 256>>>(sp, ed, mk);

    dim3 go(MROWS/64, HID/64);         // 128 x 12
    oproj_kernel<<<go, 256>>>(Wo, bo, out);
}

// round 2
// speedup vs baseline: 1.9400x; 1.9400x over previous
#include <cuda_runtime.h>
#include <stdint.h>

#define NH   12
#define SQ   1024
#define NB   8
#define HID  768
#define MROWS (NB*SQ)   // 8192

// Scratch (allocation-free rule: device globals)
__device__ float g_q[MROWS*HID];
__device__ float g_k[MROWS*HID];
__device__ float g_v[MROWS*HID];
__device__ float g_attn[MROWS*HID];

// ---------------------------------------------------------------------------
// GEMM: out[m][n] = sum_k X[m][k] * W[n][k] + bias[n]
// (fp32 FFMA floor already reached; unchanged this round)
// ---------------------------------------------------------------------------
__device__ __forceinline__ void gemm768(const float* __restrict__ X,
                                        const float* __restrict__ W,
                                        const float* __restrict__ bias,
                                        float* __restrict__ out)
{
    __shared__ __align__(16) float As[16][68];
    __shared__ __align__(16) float Bs[16][68];

    const int tid = threadIdx.x;
    const int m0 = blockIdx.x * 64;
    const int n0 = blockIdx.y * 64;
    const int lr = tid >> 2;
    const int lc = tid & 3;
    const int tx = tid & 15;
    const int ty = tid >> 4;

    float acc[4][4];
#pragma unroll
    for (int i = 0; i < 4; i++)
#pragma unroll
        for (int j = 0; j < 4; j++) acc[i][j] = 0.f;

    const float* xp = X + (m0 + lr) * HID + lc * 4;
    const float* wp = W + (n0 + lr) * HID + lc * 4;

    for (int k0 = 0; k0 < HID; k0 += 16) {
        float4 a = *(const float4*)(xp + k0);
        float4 w = *(const float4*)(wp + k0);
        As[lc*4+0][lr] = a.x; As[lc*4+1][lr] = a.y;
        As[lc*4+2][lr] = a.z; As[lc*4+3][lr] = a.w;
        Bs[lc*4+0][lr] = w.x; Bs[lc*4+1][lr] = w.y;
        Bs[lc*4+2][lr] = w.z; Bs[lc*4+3][lr] = w.w;
        __syncthreads();
#pragma unroll
        for (int kk = 0; kk < 16; kk++) {
            float4 av = *(const float4*)&As[kk][ty*4];
            float4 bv = *(const float4*)&Bs[kk][tx*4];
            float ar[4] = {av.x, av.y, av.z, av.w};
            float br[4] = {bv.x, bv.y, bv.z, bv.w};
#pragma unroll
            for (int i = 0; i < 4; i++)
#pragma unroll
                for (int j = 0; j < 4; j++)
                    acc[i][j] += ar[i] * br[j];
        }
        __syncthreads();
    }

    const int nc = n0 + tx * 4;
    float4 bb = *(const float4*)(bias + nc);
#pragma unroll
    for (int i = 0; i < 4; i++) {
        float4 o;
        o.x = acc[i][0] + bb.x;
        o.y = acc[i][1] + bb.y;
        o.z = acc[i][2] + bb.z;
        o.w = acc[i][3] + bb.w;
        *(float4*)(out + (m0 + ty*4 + i) * HID + nc) = o;
    }
}

__global__ void __launch_bounds__(256) qkv_kernel(const float* __restrict__ X,
    const float* __restrict__ Wq, const float* __restrict__ bq,
    const float* __restrict__ Wk, const float* __restrict__ bk,
    const float* __restrict__ Wv, const float* __restrict__ bv)
{
    const float* W; const float* b; float* out;
    if (blockIdx.z == 0)      { W = Wq; b = bq; out = g_q; }
    else if (blockIdx.z == 1) { W = Wk; b = bk; out = g_k; }
    else                      { W = Wv; b = bv; out = g_v; }
    gemm768(X, W, b, out);
}

__global__ void __launch_bounds__(256) oproj_kernel(const float* __restrict__ Wo,
                                                    const float* __restrict__ bo,
                                                    float* __restrict__ out)
{
    gemm768(g_attn, Wo, bo, out);
}

// ---------------------------------------------------------------------------
// Fast exp on the FMA pipe (no MUFU). Valid for x <= 0 (softmax domain).
// exp(x) = 2^(x*log2e); i = round, f in [-0.5,0.5], degree-5 Taylor for 2^f.
// Max rel err ~2.4e-6.
// ---------------------------------------------------------------------------
__device__ __forceinline__ float fexp(float x)
{
    float y = fmaxf(x * 1.4426950408889634f, -126.0f);
    int   i = __float2int_rn(y);
    float f = y - (float)i;
    float p = 1.3333558146e-3f;
    p = fmaf(p, f, 9.6181291918e-3f);
    p = fmaf(p, f, 5.5504108664e-2f);
    p = fmaf(p, f, 2.4022650696e-1f);
    p = fmaf(p, f, 6.9314718056e-1f);
    p = fmaf(p, f, 1.0f);
    float s = __int_as_float((i + 127) << 23);
    return p * s;
}

// ---------------------------------------------------------------------------
// Flash attention v2: 128 threads/CTA, each thread owns 4 q-rows x 8 cols.
// Q and K stored d-major (transposed) -> per-d outer product: 3x LDS.128
// feeds 32 FMA. P stored transposed with XOR swizzle for conflict-free PV.
// smem: Qt 16KB + KPt 16KB (K^T, reused as P^T) + Vs 16KB = 48KB static.
// ---------------------------------------------------------------------------
__global__ void __launch_bounds__(128, 4) attn_kernel(const float* __restrict__ sp,
                                                      const float* __restrict__ ed,
                                                      const unsigned char* __restrict__ mk)
{
    __shared__ __align__(16) float Qt[64*64];   // [d][qrow], pre-scaled by 0.125
    __shared__ __align__(16) float KPt[64*64];  // K^T [d][kcol]; reused as P^T [kcol][qrow^swz]
    __shared__ __align__(16) float Vs[64*64];   // [kcol][d]

    const int tid = threadIdx.x;
    const int b  = blockIdx.y / NH;
    const int h  = blockIdx.y % NH;
    const int q0 = blockIdx.x * 64;

    const int rg = tid >> 3;        // 0..15 : q-row group (4 rows)
    const int cg = tid & 7;         // 0..7  : col group (8 cols)
    const int r4 = rg * 4;
    const int c0 = cg * 8;

    // loader mapping: row lr = tid>>1 (0..63), half hf = tid&1 (32 floats)
    const int lr = tid >> 1;
    const int hf = tid & 1;
    const int d0 = hf * 32;

    // ---- load + transpose Q (scaled by 1/sqrt(64)) ----
    {
        const float4* qsrc = (const float4*)(g_q + ((size_t)(b*SQ + q0 + lr))*HID + h*64 + d0);
#pragma unroll
        for (int i = 0; i < 8; i++) {
            float4 t = qsrc[i];
            int d = d0 + i*4;
            Qt[(d+0)*64 + lr] = t.x * 0.125f;
            Qt[(d+1)*64 + lr] = t.y * 0.125f;
            Qt[(d+2)*64 + lr] = t.z * 0.125f;
            Qt[(d+3)*64 + lr] = t.w * 0.125f;
        }
    }

    float m_i[4], l_i[4];
    float acc[4][8];
#pragma unroll
    for (int i = 0; i < 4; i++) {
        m_i[i] = -1e30f; l_i[i] = 0.f;
#pragma unroll
        for (int j = 0; j < 8; j++) acc[i][j] = 0.f;
    }

    const size_t biasBase = (size_t)b * SQ * SQ + (size_t)(q0 + r4) * SQ;

    for (int kt = 0; kt < 16; kt++) {
        const int k0 = kt * 64;
        __syncthreads();  // prior PV reads of KPt/Vs done; Qt store (first iter)

        // ---- load K (transposed) and V (row-major) ----
        {
            const float4* ks = (const float4*)(g_k + ((size_t)(b*SQ + k0 + lr))*HID + h*64 + d0);
#pragma unroll
            for (int i = 0; i < 8; i++) {
                float4 t = ks[i];
                int d = d0 + i*4;
                KPt[(d+0)*64 + lr] = t.x;
                KPt[(d+1)*64 + lr] = t.y;
                KPt[(d+2)*64 + lr] = t.z;
                KPt[(d+3)*64 + lr] = t.w;
            }
            const float4* vsrc = (const float4*)(g_v + ((size_t)(b*SQ + k0 + lr))*HID + h*64 + d0);
            float4* vdst = (float4*)(Vs + lr*64 + d0);
#pragma unroll
            for (int i = 0; i < 8; i++) vdst[i] = vsrc[i];
        }
        __syncthreads();

        // ---- scores: bias first, then Q.K^T outer-product accumulation ----
        float sv[4][8];
#pragma unroll
        for (int i = 0; i < 4; i++) {
            const size_t bb = biasBase + (size_t)i * SQ + k0 + c0;
            float4 s0 = *(const float4*)(sp + bb);
            float4 s1 = *(const float4*)(sp + bb + 4);
            float4 e0 = *(const float4*)(ed + bb);
            float4 e1 = *(const float4*)(ed + bb + 4);
            sv[i][0] = s0.x + e0.x; sv[i][1] = s0.y + e0.y;
            sv[i][2] = s0.z + e0.z; sv[i][3] = s0.w + e0.w;
            sv[i][4] = s1.x + e1.x; sv[i][5] = s1.y + e1.y;
            sv[i][6] = s1.z + e1.z; sv[i][7] = s1.w + e1.w;
            uint2 mv = *(const uint2*)(mk + bb);
#pragma unroll
            for (int bi = 0; bi < 4; bi++) {
                if ((mv.x >> (8*bi)) & 0xffu) sv[i][bi]   = -1e30f;
                if ((mv.y >> (8*bi)) & 0xffu) sv[i][4+bi] = -1e30f;
            }
        }

#pragma unroll 4
        for (int d = 0; d < 64; d++) {
            float4 a4 = *(const float4*)&Qt[d*64 + r4];
            float4 b0 = *(const float4*)&KPt[d*64 + c0];
            float4 b1 = *(const float4*)&KPt[d*64 + c0 + 4];
            float ar[4] = {a4.x, a4.y, a4.z, a4.w};
            float br[8] = {b0.x, b0.y, b0.z, b0.w, b1.x, b1.y, b1.z, b1.w};
#pragma unroll
            for (int i = 0; i < 4; i++)
#pragma unroll
                for (int j = 0; j < 8; j++)
                    sv[i][j] = fmaf(ar[i], br[j], sv[i][j]);
        }

        // ---- online softmax (rowwise over 8 lanes sharing rg) ----
#pragma unroll
        for (int i = 0; i < 4; i++) {
            float mx = sv[i][0];
#pragma unroll
            for (int j = 1; j < 8; j++) mx = fmaxf(mx, sv[i][j]);
            mx = fmaxf(mx, __shfl_xor_sync(0xffffffffu, mx, 1));
            mx = fmaxf(mx, __shfl_xor_sync(0xffffffffu, mx, 2));
            mx = fmaxf(mx, __shfl_xor_sync(0xffffffffu, mx, 4));
            float m_new = fmaxf(m_i[i], mx);
            float alpha = fexp(m_i[i] - m_new);
            float ps = 0.f;
#pragma unroll
            for (int j = 0; j < 8; j++) {
                sv[i][j] = fexp(sv[i][j] - m_new);
                ps += sv[i][j];
            }
            ps += __shfl_xor_sync(0xffffffffu, ps, 1);
            ps += __shfl_xor_sync(0xffffffffu, ps, 2);
            ps += __shfl_xor_sync(0xffffffffu, ps, 4);
            l_i[i] = l_i[i] * alpha + ps;
            m_i[i] = m_new;
#pragma unroll
            for (int j = 0; j < 8; j++) acc[i][j] *= alpha;
        }

        __syncthreads();  // done reading KPt as K

        // ---- write P^T with XOR swizzle: row index (r4 ^ cg*4) within col c ----
        {
            const int rsw = r4 ^ (cg * 4);
#pragma unroll
            for (int j = 0; j < 8; j++) {
                float4 pv = make_float4(sv[0][j], sv[1][j], sv[2][j], sv[3][j]);
                *(float4*)&KPt[(c0 + j)*64 + rsw] = pv;
            }
        }
        __syncthreads();

        // ---- acc += P @ V ----
#pragma unroll 4
        for (int c = 0; c < 64; c++) {
            const int s = ((c >> 3) & 7) * 4;
            float4 p4 = *(const float4*)&KPt[c*64 + (r4 ^ s)];
            float4 v0 = *(const float4*)&Vs[c*64 + c0];
            float4 v1 = *(const float4*)&Vs[c*64 + c0 + 4];
            float pr[4] = {p4.x, p4.y, p4.z, p4.w};
            float vr[8] = {v0.x, v0.y, v0.z, v0.w, v1.x, v1.y, v1.z, v1.w};
#pragma unroll
            for (int i = 0; i < 4; i++)
#pragma unroll
                for (int j = 0; j < 8; j++)
                    acc[i][j] = fmaf(pr[i], vr[j], acc[i][j]);
        }
    }

    // ---- normalize + write ----
#pragma unroll
    for (int i = 0; i < 4; i++) {
        float inv = 1.f / l_i[i];
        float* op = g_attn + ((size_t)(b*SQ + q0 + r4 + i))*HID + h*64 + c0;
        *(float4*)(op)     = make_float4(acc[i][0]*inv, acc[i][1]*inv, acc[i][2]*inv, acc[i][3]*inv);
        *(float4*)(op + 4) = make_float4(acc[i][4]*inv, acc[i][5]*inv, acc[i][6]*inv, acc[i][7]*inv);
    }
}

// ---------------------------------------------------------------------------
extern "C" void kernel_launch(void* const* d_in, const int* in_sizes, int n_in,
                              void* d_out, int out_size)
{
    const float* x  = (const float*)d_in[0];
    const float* sp = (const float*)d_in[1];
    const float* ed = (const float*)d_in[2];
    const unsigned char* mk = (const unsigned char*)d_in[3];
    const float* Wq = (const float*)d_in[4];
    const float* bq = (const float*)d_in[5];
    const float* Wk = (const float*)d_in[6];
    const float* bk = (const float*)d_in[7];
    const float* Wv = (const float*)d_in[8];
    const float* bv = (const float*)d_in[9];
    const float* Wo = (const float*)d_in[10];
    const float* bo = (const float*)d_in[11];
    float* out = (float*)d_out;

    dim3 gq(MROWS/64, HID/64, 3);
    qkv_kernel<<<gq, 256>>>(x, Wq, bq, Wk, bk, Wv, bv);

    dim3 ga(SQ/64, NB*NH);
    attn_kernel<<<ga, 128>>>(sp, ed, mk);

    dim3 go(MROWS/64, HID/64);
    oproj_kernel<<<go, 256>>>(Wo, bo, out);
}

// round 3
// speedup vs baseline: 2.8299x; 1.4587x over previous
#include <cuda_runtime.h>
#include <cuda_bf16.h>
#include <stdint.h>

#define NH   12
#define SQ   1024
#define NB   8
#define HID  768
#define MROWS (NB*SQ)   // 8192
#define LDT  40         // padded bf16 row stride in smem tiles (80B: conflict-free ldmatrix)

// Scratch (allocation-free rule: device globals)
__device__ float g_q[MROWS*HID];
__device__ float g_k[MROWS*HID];
__device__ float g_v[MROWS*HID];
__device__ float g_attn[MROWS*HID];

// ---------------------------------------------------------------------------
// Tensor-core primitives
// ---------------------------------------------------------------------------
__device__ __forceinline__ void mma_bf16(float* d, const uint32_t* a, const uint32_t* b)
{
    asm volatile(
        "mma.sync.aligned.m16n8k16.row.col.f32.bf16.bf16.f32 "
        "{%0,%1,%2,%3},{%4,%5,%6,%7},{%8,%9},{%0,%1,%2,%3};"
        : "+f"(d[0]), "+f"(d[1]), "+f"(d[2]), "+f"(d[3])
        : "r"(a[0]), "r"(a[1]), "r"(a[2]), "r"(a[3]), "r"(b[0]), "r"(b[1]));
}
__device__ __forceinline__ void ldsm4(uint32_t* r, uint32_t addr)
{
    asm volatile("ldmatrix.sync.aligned.m8n8.x4.shared.b16 {%0,%1,%2,%3},[%4];"
                 : "=r"(r[0]), "=r"(r[1]), "=r"(r[2]), "=r"(r[3]) : "r"(addr));
}
__device__ __forceinline__ void ldsm2(uint32_t* r, uint32_t addr)
{
    asm volatile("ldmatrix.sync.aligned.m8n8.x2.shared.b16 {%0,%1},[%2];"
                 : "=r"(r[0]), "=r"(r[1]) : "r"(addr));
}

// split x into hi (bf16) + lo (bf16 of residual): x ~= hi + lo with ~2^-17 error
__device__ __forceinline__ void split4(float4 v, __nv_bfloat162& h0, __nv_bfloat162& h1,
                                       __nv_bfloat162& l0, __nv_bfloat162& l1)
{
    __nv_bfloat16 hx = __float2bfloat16_rn(v.x);
    __nv_bfloat16 hy = __float2bfloat16_rn(v.y);
    __nv_bfloat16 hz = __float2bfloat16_rn(v.z);
    __nv_bfloat16 hw = __float2bfloat16_rn(v.w);
    h0 = __nv_bfloat162(hx, hy);
    h1 = __nv_bfloat162(hz, hw);
    l0 = __nv_bfloat162(__float2bfloat16_rn(v.x - __bfloat162float(hx)),
                        __float2bfloat16_rn(v.y - __bfloat162float(hy)));
    l1 = __nv_bfloat162(__float2bfloat16_rn(v.z - __bfloat162float(hz)),
                        __float2bfloat16_rn(v.w - __bfloat162float(hw)));
}

// ---------------------------------------------------------------------------
// bf16-split tensor-core GEMM: out[m][n] = sum_k X[m][k]*W[n][k] + bias[n]
// CTA tile 128x128, BK=32, 256 threads = 8 warps (2x4), warp tile 64x32.
// C = Ahi*Bhi + Alo*Bhi + Ahi*Blo  (fp32 accum in mma)
// ---------------------------------------------------------------------------
__device__ void gemm_mma(const float* __restrict__ X, const float* __restrict__ W,
                         const float* __restrict__ bias, float* __restrict__ out)
{
    __shared__ __align__(16) __nv_bfloat16 sAhi[128*LDT];
    __shared__ __align__(16) __nv_bfloat16 sAlo[128*LDT];
    __shared__ __align__(16) __nv_bfloat16 sBhi[128*LDT];
    __shared__ __align__(16) __nv_bfloat16 sBlo[128*LDT];

    const int tid  = threadIdx.x;
    const int lane = tid & 31;
    const int wid  = tid >> 5;
    const int wm   = (wid >> 2) * 64;   // warp m offset within CTA
    const int wn   = (wid & 3) * 32;    // warp n offset within CTA
    const int m0   = blockIdx.x * 128;
    const int n0   = blockIdx.y * 128;

    const int lrow = tid >> 3;          // 0..31 loader row
    const int lch  = (tid & 7) * 4;     // loader k-offset (float4)

    float acc[4][4][4];
#pragma unroll
    for (int mt = 0; mt < 4; mt++)
#pragma unroll
        for (int nt = 0; nt < 4; nt++)
#pragma unroll
            for (int r = 0; r < 4; r++) acc[mt][nt][r] = 0.f;

    const uint32_t aHi = (uint32_t)__cvta_generic_to_shared(sAhi);
    const uint32_t aLo = (uint32_t)__cvta_generic_to_shared(sAlo);
    const uint32_t bHi = (uint32_t)__cvta_generic_to_shared(sBhi);
    const uint32_t bLo = (uint32_t)__cvta_generic_to_shared(sBlo);
    const uint32_t aOff = ((wm + (lane & 15)) * LDT + (lane >> 4) * 8) * 2;
    const uint32_t bOff = ((wn + (lane & 7)) * LDT + ((lane >> 3) & 1) * 8) * 2;

    const float* Xp = X + (size_t)(m0 + lrow) * HID + lch;
    const float* Wp = W + (size_t)(n0 + lrow) * HID + lch;

    float4 pa[4], pb[4];
#pragma unroll
    for (int i = 0; i < 4; i++) {
        pa[i] = *(const float4*)(Xp + (size_t)i * 32 * HID);
        pb[i] = *(const float4*)(Wp + (size_t)i * 32 * HID);
    }

    for (int k0 = 0; k0 < HID; k0 += 32) {
        // store prefetched tile (split into hi/lo)
#pragma unroll
        for (int i = 0; i < 4; i++) {
            int e = (lrow + 32 * i) * LDT + lch;
            __nv_bfloat162 h0, h1, l0, l1;
            split4(pa[i], h0, h1, l0, l1);
            *(__nv_bfloat162*)(sAhi + e)     = h0;
            *(__nv_bfloat162*)(sAhi + e + 2) = h1;
            *(__nv_bfloat162*)(sAlo + e)     = l0;
            *(__nv_bfloat162*)(sAlo + e + 2) = l1;
            split4(pb[i], h0, h1, l0, l1);
            *(__nv_bfloat162*)(sBhi + e)     = h0;
            *(__nv_bfloat162*)(sBhi + e + 2) = h1;
            *(__nv_bfloat162*)(sBlo + e)     = l0;
            *(__nv_bfloat162*)(sBlo + e + 2) = l1;
        }
        __syncthreads();

        // prefetch next k-tile (hidden under the MMAs below)
        if (k0 + 32 < HID) {
#pragma unroll
            for (int i = 0; i < 4; i++) {
                pa[i] = *(const float4*)(Xp + k0 + 32 + (size_t)i * 32 * HID);
                pb[i] = *(const float4*)(Wp + k0 + 32 + (size_t)i * 32 * HID);
            }
        }

#pragma unroll
        for (int ks = 0; ks < 32; ks += 16) {
            uint32_t ah[4][4], al[4][4];
#pragma unroll
            for (int mt = 0; mt < 4; mt++) {
                uint32_t off = aOff + (uint32_t)(mt * 16 * LDT + ks) * 2;
                ldsm4(ah[mt], aHi + off);
                ldsm4(al[mt], aLo + off);
            }
#pragma unroll
            for (int nt = 0; nt < 4; nt++) {
                uint32_t off = bOff + (uint32_t)(nt * 8 * LDT + ks) * 2;
                uint32_t bh[2], bl[2];
                ldsm2(bh, bHi + off);
                ldsm2(bl, bLo + off);
#pragma unroll
                for (int mt = 0; mt < 4; mt++) {
                    mma_bf16(acc[mt][nt], ah[mt], bh);
                    mma_bf16(acc[mt][nt], al[mt], bh);
                    mma_bf16(acc[mt][nt], ah[mt], bl);
                }
            }
        }
        __syncthreads();
    }

    // epilogue: +bias, write fp32
    const int g = lane >> 2;
    const int t = (lane & 3) * 2;
#pragma unroll
    for (int nt = 0; nt < 4; nt++) {
        const int nc = n0 + wn + nt * 8 + t;
        float2 bb = *(const float2*)(bias + nc);
#pragma unroll
        for (int mt = 0; mt < 4; mt++) {
            const int mr = m0 + wm + mt * 16 + g;
            float2 o0 = make_float2(acc[mt][nt][0] + bb.x, acc[mt][nt][1] + bb.y);
            float2 o1 = make_float2(acc[mt][nt][2] + bb.x, acc[mt][nt][3] + bb.y);
            *(float2*)(out + (size_t)mr * HID + nc)       = o0;
            *(float2*)(out + (size_t)(mr + 8) * HID + nc) = o1;
        }
    }
}

__global__ void __launch_bounds__(256) qkv_kernel(const float* __restrict__ X,
    const float* __restrict__ Wq, const float* __restrict__ bq,
    const float* __restrict__ Wk, const float* __restrict__ bk,
    const float* __restrict__ Wv, const float* __restrict__ bv)
{
    const float* W; const float* b; float* out;
    if (blockIdx.z == 0)      { W = Wq; b = bq; out = g_q; }
    else if (blockIdx.z == 1) { W = Wk; b = bk; out = g_k; }
    else                      { W = Wv; b = bv; out = g_v; }
    gemm_mma(X, W, b, out);
}

__global__ void __launch_bounds__(256) oproj_kernel(const float* __restrict__ Wo,
                                                    const float* __restrict__ bo,
                                                    float* __restrict__ out)
{
    gemm_mma(g_attn, Wo, bo, out);
}

// ---------------------------------------------------------------------------
// Fast exp on the FMA pipe (no MUFU). Valid for x <= 0 (softmax domain).
// ---------------------------------------------------------------------------
__device__ __forceinline__ float fexp(float x)
{
    float y = fmaxf(x * 1.4426950408889634f, -126.0f);
    int   i = __float2int_rn(y);
    float f = y - (float)i;
    float p = 1.3333558146e-3f;
    p = fmaf(p, f, 9.6181291918e-3f);
    p = fmaf(p, f, 5.5504108664e-2f);
    p = fmaf(p, f, 2.4022650696e-1f);
    p = fmaf(p, f, 6.9314718056e-1f);
    p = fmaf(p, f, 1.0f);
    float s = __int_as_float((i + 127) << 23);
    return p * s;
}

// ---------------------------------------------------------------------------
// Flash attention: 128 threads/CTA, each thread owns 4 q-rows x 8 cols.
// (unchanged from round 2 — tensor-core port is next round)
// ---------------------------------------------------------------------------
__global__ void __launch_bounds__(128, 4) attn_kernel(const float* __restrict__ sp,
                                                      const float* __restrict__ ed,
                                                      const unsigned char* __restrict__ mk)
{
    __shared__ __align__(16) float Qt[64*64];
    __shared__ __align__(16) float KPt[64*64];
    __shared__ __align__(16) float Vs[64*64];

    const int tid = threadIdx.x;
    const int b  = blockIdx.y / NH;
    const int h  = blockIdx.y % NH;
    const int q0 = blockIdx.x * 64;

    const int rg = tid >> 3;
    const int cg = tid & 7;
    const int r4 = rg * 4;
    const int c0 = cg * 8;

    const int lr = tid >> 1;
    const int hf = tid & 1;
    const int d0 = hf * 32;

    {
        const float4* qsrc = (const float4*)(g_q + ((size_t)(b*SQ + q0 + lr))*HID + h*64 + d0);
#pragma unroll
        for (int i = 0; i < 8; i++) {
            float4 t = qsrc[i];
            int d = d0 + i*4;
            Qt[(d+0)*64 + lr] = t.x * 0.125f;
            Qt[(d+1)*64 + lr] = t.y * 0.125f;
            Qt[(d+2)*64 + lr] = t.z * 0.125f;
            Qt[(d+3)*64 + lr] = t.w * 0.125f;
        }
    }

    float m_i[4], l_i[4];
    float acc[4][8];
#pragma unroll
    for (int i = 0; i < 4; i++) {
        m_i[i] = -1e30f; l_i[i] = 0.f;
#pragma unroll
        for (int j = 0; j < 8; j++) acc[i][j] = 0.f;
    }

    const size_t biasBase = (size_t)b * SQ * SQ + (size_t)(q0 + r4) * SQ;

    for (int kt = 0; kt < 16; kt++) {
        const int k0 = kt * 64;
        __syncthreads();

        {
            const float4* ks = (const float4*)(g_k + ((size_t)(b*SQ + k0 + lr))*HID + h*64 + d0);
#pragma unroll
            for (int i = 0; i < 8; i++) {
                float4 t = ks[i];
                int d = d0 + i*4;
                KPt[(d+0)*64 + lr] = t.x;
                KPt[(d+1)*64 + lr] = t.y;
                KPt[(d+2)*64 + lr] = t.z;
                KPt[(d+3)*64 + lr] = t.w;
            }
            const float4* vsrc = (const float4*)(g_v + ((size_t)(b*SQ + k0 + lr))*HID + h*64 + d0);
            float4* vdst = (float4*)(Vs + lr*64 + d0);
#pragma unroll
            for (int i = 0; i < 8; i++) vdst[i] = vsrc[i];
        }
        __syncthreads();

        float sv[4][8];
#pragma unroll
        for (int i = 0; i < 4; i++) {
            const size_t bb = biasBase + (size_t)i * SQ + k0 + c0;
            float4 s0 = *(const float4*)(sp + bb);
            float4 s1 = *(const float4*)(sp + bb + 4);
            float4 e0 = *(const float4*)(ed + bb);
            float4 e1 = *(const float4*)(ed + bb + 4);
            sv[i][0] = s0.x + e0.x; sv[i][1] = s0.y + e0.y;
            sv[i][2] = s0.z + e0.z; sv[i][3] = s0.w + e0.w;
            sv[i][4] = s1.x + e1.x; sv[i][5] = s1.y + e1.y;
            sv[i][6] = s1.z + e1.z; sv[i][7] = s1.w + e1.w;
            uint2 mv = *(const uint2*)(mk + bb);
#pragma unroll
            for (int bi = 0; bi < 4; bi++) {
                if ((mv.x >> (8*bi)) & 0xffu) sv[i][bi]   = -1e30f;
                if ((mv.y >> (8*bi)) & 0xffu) sv[i][4+bi] = -1e30f;
            }
        }

#pragma unroll 4
        for (int d = 0; d < 64; d++) {
            float4 a4 = *(const float4*)&Qt[d*64 + r4];
            float4 b0 = *(const float4*)&KPt[d*64 + c0];
            float4 b1 = *(const float4*)&KPt[d*64 + c0 + 4];
            float ar[4] = {a4.x, a4.y, a4.z, a4.w};
            float br[8] = {b0.x, b0.y, b0.z, b0.w, b1.x, b1.y, b1.z, b1.w};
#pragma unroll
            for (int i = 0; i < 4; i++)
#pragma unroll
                for (int j = 0; j < 8; j++)
                    sv[i][j] = fmaf(ar[i], br[j], sv[i][j]);
        }

#pragma unroll
        for (int i = 0; i < 4; i++) {
            float mx = sv[i][0];
#pragma unroll
            for (int j = 1; j < 8; j++) mx = fmaxf(mx, sv[i][j]);
            mx = fmaxf(mx, __shfl_xor_sync(0xffffffffu, mx, 1));
            mx = fmaxf(mx, __shfl_xor_sync(0xffffffffu, mx, 2));
            mx = fmaxf(mx, __shfl_xor_sync(0xffffffffu, mx, 4));
            float m_new = fmaxf(m_i[i], mx);
            float alpha = fexp(m_i[i] - m_new);
            float ps = 0.f;
#pragma unroll
            for (int j = 0; j < 8; j++) {
                sv[i][j] = fexp(sv[i][j] - m_new);
                ps += sv[i][j];
            }
            ps += __shfl_xor_sync(0xffffffffu, ps, 1);
            ps += __shfl_xor_sync(0xffffffffu, ps, 2);
            ps += __shfl_xor_sync(0xffffffffu, ps, 4);
            l_i[i] = l_i[i] * alpha + ps;
            m_i[i] = m_new;
#pragma unroll
            for (int j = 0; j < 8; j++) acc[i][j] *= alpha;
        }

        __syncthreads();

        {
            const int rsw = r4 ^ (cg * 4);
#pragma unroll
            for (int j = 0; j < 8; j++) {
                float4 pv = make_float4(sv[0][j], sv[1][j], sv[2][j], sv[3][j]);
                *(float4*)&KPt[(c0 + j)*64 + rsw] = pv;
            }
        }
        __syncthreads();

#pragma unroll 4
        for (int c = 0; c < 64; c++) {
            const int s = ((c >> 3) & 7) * 4;
            float4 p4 = *(const float4*)&KPt[c*64 + (r4 ^ s)];
            float4 v0 = *(const float4*)&Vs[c*64 + c0];
            float4 v1 = *(const float4*)&Vs[c*64 + c0 + 4];
            float pr[4] = {p4.x, p4.y, p4.z, p4.w};
            float vr[8] = {v0.x, v0.y, v0.z, v0.w, v1.x, v1.y, v1.z, v1.w};
#pragma unroll
            for (int i = 0; i < 4; i++)
#pragma unroll
                for (int j = 0; j < 8; j++)
                    acc[i][j] = fmaf(pr[i], vr[j], acc[i][j]);
        }
    }

#pragma unroll
    for (int i = 0; i < 4; i++) {
        float inv = 1.f / l_i[i];
        float* op = g_attn + ((size_t)(b*SQ + q0 + r4 + i))*HID + h*64 + c0;
        *(float4*)(op)     = make_float4(acc[i][0]*inv, acc[i][1]*inv, acc[i][2]*inv, acc[i][3]*inv);
        *(float4*)(op + 4) = make_float4(acc[i][4]*inv, acc[i][5]*inv, acc[i][6]*inv, acc[i][7]*inv);
    }
}

// ---------------------------------------------------------------------------
extern "C" void kernel_launch(void* const* d_in, const int* in_sizes, int n_in,
                              void* d_out, int out_size)
{
    const float* x  = (const float*)d_in[0];
    const float* sp = (const float*)d_in[1];
    const float* ed = (const float*)d_in[2];
    const unsigned char* mk = (const unsigned char*)d_in[3];
    const float* Wq = (const float*)d_in[4];
    const float* bq = (const float*)d_in[5];
    const float* Wk = (const float*)d_in[6];
    const float* bk = (const float*)d_in[7];
    const float* Wv = (const float*)d_in[8];
    const float* bv = (const float*)d_in[9];
    const float* Wo = (const float*)d_in[10];
    const float* bo = (const float*)d_in[11];
    float* out = (float*)d_out;

    dim3 gq(MROWS/128, HID/128, 3);     // 64 x 6 x 3
    qkv_kernel<<<gq, 256>>>(x, Wq, bq, Wk, bk, Wv, bv);

    dim3 ga(SQ/64, NB*NH);              // 16 x 96
    attn_kernel<<<ga, 128>>>(sp, ed, mk);

    dim3 go(MROWS/128, HID/128);        // 64 x 6
    oproj_kernel<<<go, 256>>>(Wo, bo, out);
}

// round 5
// speedup vs baseline: 4.3885x; 1.5508x over previous
#include <cuda_runtime.h>
#include <cuda_bf16.h>
#include <stdint.h>

#define NH   12
#define SQ   1024
#define NB   8
#define HID  768
#define MROWS (NB*SQ)   // 8192
#define LDT  40         // GEMM: padded bf16 row stride (32 k-cols + 8)
#define ALD  72         // attention K/V tiles: 64 d-cols + 8 pad

// Scratch (allocation-free rule: device globals)
__device__ float g_q[MROWS*HID];
__device__ float g_k[MROWS*HID];
__device__ float g_v[MROWS*HID];
__device__ float g_attn[MROWS*HID];

// ---------------------------------------------------------------------------
// Tensor-core primitives
// ---------------------------------------------------------------------------
__device__ __forceinline__ void mma_bf16(float* d, const uint32_t* a, const uint32_t* b)
{
    asm volatile(
        "mma.sync.aligned.m16n8k16.row.col.f32.bf16.bf16.f32 "
        "{%0,%1,%2,%3},{%4,%5,%6,%7},{%8,%9},{%0,%1,%2,%3};"
        : "+f"(d[0]), "+f"(d[1]), "+f"(d[2]), "+f"(d[3])
        : "r"(a[0]), "r"(a[1]), "r"(a[2]), "r"(a[3]), "r"(b[0]), "r"(b[1]));
}
__device__ __forceinline__ void ldsm4(uint32_t* r, uint32_t addr)
{
    asm volatile("ldmatrix.sync.aligned.m8n8.x4.shared.b16 {%0,%1,%2,%3},[%4];"
                 : "=r"(r[0]), "=r"(r[1]), "=r"(r[2]), "=r"(r[3]) : "r"(addr));
}
__device__ __forceinline__ void ldsm2(uint32_t* r, uint32_t addr)
{
    asm volatile("ldmatrix.sync.aligned.m8n8.x2.shared.b16 {%0,%1},[%2];"
                 : "=r"(r[0]), "=r"(r[1]) : "r"(addr));
}
__device__ __forceinline__ void ldsm2t(uint32_t* r, uint32_t addr)
{
    asm volatile("ldmatrix.sync.aligned.m8n8.x2.trans.shared.b16 {%0,%1},[%2];"
                 : "=r"(r[0]), "=r"(r[1]) : "r"(addr));
}

// split x into hi (bf16) + lo (bf16 of residual)
__device__ __forceinline__ void split4(float4 v, __nv_bfloat162& h0, __nv_bfloat162& h1,
                                       __nv_bfloat162& l0, __nv_bfloat162& l1)
{
    __nv_bfloat16 hx = __float2bfloat16_rn(v.x);
    __nv_bfloat16 hy = __float2bfloat16_rn(v.y);
    __nv_bfloat16 hz = __float2bfloat16_rn(v.z);
    __nv_bfloat16 hw = __float2bfloat16_rn(v.w);
    h0 = __nv_bfloat162(hx, hy);
    h1 = __nv_bfloat162(hz, hw);
    l0 = __nv_bfloat162(__float2bfloat16_rn(v.x - __bfloat162float(hx)),
                        __float2bfloat16_rn(v.y - __bfloat162float(hy)));
    l1 = __nv_bfloat162(__float2bfloat16_rn(v.z - __bfloat162float(hz)),
                        __float2bfloat16_rn(v.w - __bfloat162float(hw)));
}
__device__ __forceinline__ void split2(float x, float y, uint32_t& hi, uint32_t& lo)
{
    __nv_bfloat16 hx = __float2bfloat16_rn(x);
    __nv_bfloat16 hy = __float2bfloat16_rn(y);
    __nv_bfloat162 h(hx, hy);
    __nv_bfloat162 l(__float2bfloat16_rn(x - __bfloat162float(hx)),
                     __float2bfloat16_rn(y - __bfloat162float(hy)));
    hi = *(uint32_t*)&h;
    lo = *(uint32_t*)&l;
}

// ---------------------------------------------------------------------------
// bf16-split tensor-core GEMM (validated in round 3, unchanged)
// ---------------------------------------------------------------------------
__device__ void gemm_mma(const float* __restrict__ X, const float* __restrict__ W,
                         const float* __restrict__ bias, float* __restrict__ out)
{
    __shared__ __align__(16) __nv_bfloat16 sAhi[128*LDT];
    __shared__ __align__(16) __nv_bfloat16 sAlo[128*LDT];
    __shared__ __align__(16) __nv_bfloat16 sBhi[128*LDT];
    __shared__ __align__(16) __nv_bfloat16 sBlo[128*LDT];

    const int tid  = threadIdx.x;
    const int lane = tid & 31;
    const int wid  = tid >> 5;
    const int wm   = (wid >> 2) * 64;
    const int wn   = (wid & 3) * 32;
    const int m0   = blockIdx.x * 128;
    const int n0   = blockIdx.y * 128;

    const int lrow = tid >> 3;
    const int lch  = (tid & 7) * 4;

    float acc[4][4][4];
#pragma unroll
    for (int mt = 0; mt < 4; mt++)
#pragma unroll
        for (int nt = 0; nt < 4; nt++)
#pragma unroll
            for (int r = 0; r < 4; r++) acc[mt][nt][r] = 0.f;

    const uint32_t aHi = (uint32_t)__cvta_generic_to_shared(sAhi);
    const uint32_t aLo = (uint32_t)__cvta_generic_to_shared(sAlo);
    const uint32_t bHi = (uint32_t)__cvta_generic_to_shared(sBhi);
    const uint32_t bLo = (uint32_t)__cvta_generic_to_shared(sBlo);
    const uint32_t aOff = ((wm + (lane & 15)) * LDT + (lane >> 4) * 8) * 2;
    const uint32_t bOff = ((wn + (lane & 7)) * LDT + ((lane >> 3) & 1) * 8) * 2;

    const float* Xp = X + (size_t)(m0 + lrow) * HID + lch;
    const float* Wp = W + (size_t)(n0 + lrow) * HID + lch;

    float4 pa[4], pb[4];
#pragma unroll
    for (int i = 0; i < 4; i++) {
        pa[i] = *(const float4*)(Xp + (size_t)i * 32 * HID);
        pb[i] = *(const float4*)(Wp + (size_t)i * 32 * HID);
    }

    for (int k0 = 0; k0 < HID; k0 += 32) {
#pragma unroll
        for (int i = 0; i < 4; i++) {
            int e = (lrow + 32 * i) * LDT + lch;
            __nv_bfloat162 h0, h1, l0, l1;
            split4(pa[i], h0, h1, l0, l1);
            *(__nv_bfloat162*)(sAhi + e)     = h0;
            *(__nv_bfloat162*)(sAhi + e + 2) = h1;
            *(__nv_bfloat162*)(sAlo + e)     = l0;
            *(__nv_bfloat162*)(sAlo + e + 2) = l1;
            split4(pb[i], h0, h1, l0, l1);
            *(__nv_bfloat162*)(sBhi + e)     = h0;
            *(__nv_bfloat162*)(sBhi + e + 2) = h1;
            *(__nv_bfloat162*)(sBlo + e)     = l0;
            *(__nv_bfloat162*)(sBlo + e + 2) = l1;
        }
        __syncthreads();

        if (k0 + 32 < HID) {
#pragma unroll
            for (int i = 0; i < 4; i++) {
                pa[i] = *(const float4*)(Xp + k0 + 32 + (size_t)i * 32 * HID);
                pb[i] = *(const float4*)(Wp + k0 + 32 + (size_t)i * 32 * HID);
            }
        }

#pragma unroll
        for (int ks = 0; ks < 32; ks += 16) {
            uint32_t ah[4][4], al[4][4];
#pragma unroll
            for (int mt = 0; mt < 4; mt++) {
                uint32_t off = aOff + (uint32_t)(mt * 16 * LDT + ks) * 2;
                ldsm4(ah[mt], aHi + off);
                ldsm4(al[mt], aLo + off);
            }
#pragma unroll
            for (int nt = 0; nt < 4; nt++) {
                uint32_t off = bOff + (uint32_t)(nt * 8 * LDT + ks) * 2;
                uint32_t bh[2], bl[2];
                ldsm2(bh, bHi + off);
                ldsm2(bl, bLo + off);
#pragma unroll
                for (int mt = 0; mt < 4; mt++) {
                    mma_bf16(acc[mt][nt], ah[mt], bh);
                    mma_bf16(acc[mt][nt], al[mt], bh);
                    mma_bf16(acc[mt][nt], ah[mt], bl);
                }
            }
        }
        __syncthreads();
    }

    const int g = lane >> 2;
    const int t = (lane & 3) * 2;
#pragma unroll
    for (int nt = 0; nt < 4; nt++) {
        const int nc = n0 + wn + nt * 8 + t;
        float2 bb = *(const float2*)(bias + nc);
#pragma unroll
        for (int mt = 0; mt < 4; mt++) {
            const int mr = m0 + wm + mt * 16 + g;
            float2 o0 = make_float2(acc[mt][nt][0] + bb.x, acc[mt][nt][1] + bb.y);
            float2 o1 = make_float2(acc[mt][nt][2] + bb.x, acc[mt][nt][3] + bb.y);
            *(float2*)(out + (size_t)mr * HID + nc)       = o0;
            *(float2*)(out + (size_t)(mr + 8) * HID + nc) = o1;
        }
    }
}

__global__ void __launch_bounds__(256) qkv_kernel(const float* __restrict__ X,
    const float* __restrict__ Wq, const float* __restrict__ bq,
    const float* __restrict__ Wk, const float* __restrict__ bk,
    const float* __restrict__ Wv, const float* __restrict__ bv)
{
    const float* W; const float* b; float* out;
    if (blockIdx.z == 0)      { W = Wq; b = bq; out = g_q; }
    else if (blockIdx.z == 1) { W = Wk; b = bk; out = g_k; }
    else                      { W = Wv; b = bv; out = g_v; }
    gemm_mma(X, W, b, out);
}

__global__ void __launch_bounds__(256) oproj_kernel(const float* __restrict__ Wo,
                                                    const float* __restrict__ bo,
                                                    float* __restrict__ out)
{
    gemm_mma(g_attn, Wo, bo, out);
}

// ---------------------------------------------------------------------------
// Fast exp on the FMA pipe (no MUFU). Valid for x <= 0.
// ---------------------------------------------------------------------------
__device__ __forceinline__ float fexp(float x)
{
    float y = fmaxf(x * 1.4426950408889634f, -126.0f);
    int   i = __float2int_rn(y);
    float f = y - (float)i;
    float p = 1.3333558146e-3f;
    p = fmaf(p, f, 9.6181291918e-3f);
    p = fmaf(p, f, 5.5504108664e-2f);
    p = fmaf(p, f, 2.4022650696e-1f);
    p = fmaf(p, f, 6.9314718056e-1f);
    p = fmaf(p, f, 1.0f);
    float s = __int_as_float((i + 127) << 23);
    return p * s;
}

// ---------------------------------------------------------------------------
// Tensor-core flash attention.
// CTA: 128 q-rows x one (b,h). 8 warps, each owns 16 q-rows.
// Q fragments loaded directly from gmem (known m16n8k16 A layout) -> no Q smem.
// K/V tiles in smem (ALD=72 padded stride, conflict-free ldmatrix).
// Bias+mask as C-init; QK^T and PV via 3-MMA bf16 split; softmax in regs;
// P repacked in-register into A-frags.
// ---------------------------------------------------------------------------
__global__ void __launch_bounds__(256) attn_kernel(const float* __restrict__ sp,
                                                   const float* __restrict__ ed,
                                                   const unsigned char* __restrict__ mk)
{
    __shared__ __align__(16) __nv_bfloat16 sKh[64*ALD];
    __shared__ __align__(16) __nv_bfloat16 sKl[64*ALD];
    __shared__ __align__(16) __nv_bfloat16 sVh[64*ALD];
    __shared__ __align__(16) __nv_bfloat16 sVl[64*ALD];

    const int tid  = threadIdx.x;
    const int lane = tid & 31;
    const int w    = tid >> 5;
    const int g    = lane >> 2;        // 0..7
    const int t    = lane & 3;         // 0..3
    const int b    = blockIdx.y / NH;
    const int h    = blockIdx.y % NH;
    const int q0   = blockIdx.x * 128;

    const uint32_t kHb = (uint32_t)__cvta_generic_to_shared(sKh);
    const uint32_t kLb = (uint32_t)__cvta_generic_to_shared(sKl);
    const uint32_t vHb = (uint32_t)__cvta_generic_to_shared(sVh);
    const uint32_t vLb = (uint32_t)__cvta_generic_to_shared(sVl);

    const int qrow0 = q0 + w*16 + g;        // fragment rows g / g+8

    // ---- Q fragments direct from gmem (scaled by 1/8), split hi/lo ----
    uint32_t qh[4][4], ql[4][4];
    {
        const float* rowA = g_q + ((size_t)(b*SQ + qrow0))*HID + h*64;
        const float* rowB = rowA + (size_t)8*HID;
#pragma unroll
        for (int ks = 0; ks < 4; ks++) {
            const int c = ks*16 + t*2;
            float2 v;
            v = *(const float2*)(rowA + c);
            split2(v.x*0.125f, v.y*0.125f, qh[ks][0], ql[ks][0]);
            v = *(const float2*)(rowB + c);
            split2(v.x*0.125f, v.y*0.125f, qh[ks][1], ql[ks][1]);
            v = *(const float2*)(rowA + c + 8);
            split2(v.x*0.125f, v.y*0.125f, qh[ks][2], ql[ks][2]);
            v = *(const float2*)(rowB + c + 8);
            split2(v.x*0.125f, v.y*0.125f, qh[ks][3], ql[ks][3]);
        }
    }

    float m_i[2] = {-1e30f, -1e30f};
    float l_i[2] = {0.f, 0.f};
    float oacc[8][4];
#pragma unroll
    for (int nt = 0; nt < 8; nt++)
#pragma unroll
        for (int r = 0; r < 4; r++) oacc[nt][r] = 0.f;

    const size_t bias0 = ((size_t)b*SQ + qrow0) * SQ;
    const size_t bias1 = bias0 + 8*SQ;      // row g+8

    for (int kt = 0; kt < 16; kt++) {
        const int k0 = kt * 64;

        // ---- bias + mask into score fragments (C init) ----
        float sv[8][4];
#pragma unroll
        for (int nt = 0; nt < 8; nt++) {
            const size_t c = k0 + nt*8 + t*2;
            float2 s0 = *(const float2*)(sp + bias0 + c);
            float2 e0 = *(const float2*)(ed + bias0 + c);
            float2 s1 = *(const float2*)(sp + bias1 + c);
            float2 e1 = *(const float2*)(ed + bias1 + c);
            unsigned short m0v = *(const unsigned short*)(mk + bias0 + c);
            unsigned short m1v = *(const unsigned short*)(mk + bias1 + c);
            sv[nt][0] = (m0v & 0x00ffu) ? -1e30f : s0.x + e0.x;
            sv[nt][1] = (m0v & 0xff00u) ? -1e30f : s0.y + e0.y;
            sv[nt][2] = (m1v & 0x00ffu) ? -1e30f : s1.x + e1.x;
            sv[nt][3] = (m1v & 0xff00u) ? -1e30f : s1.y + e1.y;
        }

        __syncthreads();   // previous iteration's K/V reads complete

        // ---- K, V tiles -> smem (split hi/lo) ----
        {
            const int lr = tid >> 2;            // 0..63
            const int d0 = (tid & 3) * 16;
            const float4* ksrc = (const float4*)(g_k + ((size_t)(b*SQ + k0 + lr))*HID + h*64 + d0);
            const float4* vsrc = (const float4*)(g_v + ((size_t)(b*SQ + k0 + lr))*HID + h*64 + d0);
#pragma unroll
            for (int i = 0; i < 4; i++) {
                __nv_bfloat162 h0, h1, l0, l1;
                int e = lr*ALD + d0 + i*4;
                split4(ksrc[i], h0, h1, l0, l1);
                *(__nv_bfloat162*)(sKh + e)     = h0;
                *(__nv_bfloat162*)(sKh + e + 2) = h1;
                *(__nv_bfloat162*)(sKl + e)     = l0;
                *(__nv_bfloat162*)(sKl + e + 2) = l1;
                split4(vsrc[i], h0, h1, l0, l1);
                *(__nv_bfloat162*)(sVh + e)     = h0;
                *(__nv_bfloat162*)(sVh + e + 2) = h1;
                *(__nv_bfloat162*)(sVl + e)     = l0;
                *(__nv_bfloat162*)(sVl + e + 2) = l1;
            }
        }
        __syncthreads();

        // ---- scores += Q.K^T (split: hh + lh + hl) ----
#pragma unroll
        for (int ks = 0; ks < 4; ks++) {
#pragma unroll
            for (int nt = 0; nt < 8; nt++) {
                const uint32_t boff = (uint32_t)((nt*8 + (lane & 7)) * ALD
                                     + ((lane >> 3) & 1) * 8 + ks*16) * 2;
                uint32_t kh[2], kl[2];
                ldsm2(kh, kHb + boff);
                ldsm2(kl, kLb + boff);
                mma_bf16(sv[nt], qh[ks], kh);
                mma_bf16(sv[nt], ql[ks], kh);
                mma_bf16(sv[nt], qh[ks], kl);
            }
        }

        // ---- online softmax (rows g and g+8; reduce over quad lanes) ----
        float mx0 = sv[0][0], mx1 = sv[0][2];
#pragma unroll
        for (int nt = 0; nt < 8; nt++) {
            mx0 = fmaxf(mx0, fmaxf(sv[nt][0], sv[nt][1]));
            mx1 = fmaxf(mx1, fmaxf(sv[nt][2], sv[nt][3]));
        }
        mx0 = fmaxf(mx0, __shfl_xor_sync(0xffffffffu, mx0, 1));
        mx0 = fmaxf(mx0, __shfl_xor_sync(0xffffffffu, mx0, 2));
        mx1 = fmaxf(mx1, __shfl_xor_sync(0xffffffffu, mx1, 1));
        mx1 = fmaxf(mx1, __shfl_xor_sync(0xffffffffu, mx1, 2));

        const float mn0 = fmaxf(m_i[0], mx0);
        const float mn1 = fmaxf(m_i[1], mx1);
        const float al0 = fexp(m_i[0] - mn0);
        const float al1 = fexp(m_i[1] - mn1);
        float ps0 = 0.f, ps1 = 0.f;
#pragma unroll
        for (int nt = 0; nt < 8; nt++) {
            sv[nt][0] = fexp(sv[nt][0] - mn0);
            sv[nt][1] = fexp(sv[nt][1] - mn0);
            sv[nt][2] = fexp(sv[nt][2] - mn1);
            sv[nt][3] = fexp(sv[nt][3] - mn1);
            ps0 += sv[nt][0] + sv[nt][1];
            ps1 += sv[nt][2] + sv[nt][3];
        }
        ps0 += __shfl_xor_sync(0xffffffffu, ps0, 1);
        ps0 += __shfl_xor_sync(0xffffffffu, ps0, 2);
        ps1 += __shfl_xor_sync(0xffffffffu, ps1, 1);
        ps1 += __shfl_xor_sync(0xffffffffu, ps1, 2);
        l_i[0] = l_i[0]*al0 + ps0;  m_i[0] = mn0;
        l_i[1] = l_i[1]*al1 + ps1;  m_i[1] = mn1;
#pragma unroll
        for (int nt = 0; nt < 8; nt++) {
            oacc[nt][0] *= al0; oacc[nt][1] *= al0;
            oacc[nt][2] *= al1; oacc[nt][3] *= al1;
        }

        // ---- repack P (C-frag) -> A-frags, split hi/lo ----
        uint32_t ph[4][4], pl[4][4];
#pragma unroll
        for (int ks = 0; ks < 4; ks++) {
            split2(sv[2*ks][0],   sv[2*ks][1],   ph[ks][0], pl[ks][0]);
            split2(sv[2*ks][2],   sv[2*ks][3],   ph[ks][1], pl[ks][1]);
            split2(sv[2*ks+1][0], sv[2*ks+1][1], ph[ks][2], pl[ks][2]);
            split2(sv[2*ks+1][2], sv[2*ks+1][3], ph[ks][3], pl[ks][3]);
        }

        // ---- out += P.V (V^T fragments via ldmatrix.trans) ----
#pragma unroll
        for (int ks = 0; ks < 4; ks++) {
#pragma unroll
            for (int nt = 0; nt < 8; nt++) {
                const uint32_t voff = (uint32_t)((ks*16 + (lane & 15)) * ALD + nt*8) * 2;
                uint32_t vh[2], vl[2];
                ldsm2t(vh, vHb + voff);
                ldsm2t(vl, vLb + voff);
                mma_bf16(oacc[nt], ph[ks], vh);
                mma_bf16(oacc[nt], pl[ks], vh);
                mma_bf16(oacc[nt], ph[ks], vl);
            }
        }
    }

    // ---- normalize + write ----
    const float inv0 = 1.f / l_i[0];
    const float inv1 = 1.f / l_i[1];
    float* o0 = g_attn + ((size_t)(b*SQ + qrow0))*HID + h*64 + t*2;
    float* o1 = o0 + (size_t)8 * HID;
#pragma unroll
    for (int nt = 0; nt < 8; nt++) {
        *(float2*)(o0 + nt*8) = make_float2(oacc[nt][0]*inv0, oacc[nt][1]*inv0);
        *(float2*)(o1 + nt*8) = make_float2(oacc[nt][2]*inv1, oacc[nt][3]*inv1);
    }
}

// ---------------------------------------------------------------------------
extern "C" void kernel_launch(void* const* d_in, const int* in_sizes, int n_in,
                              void* d_out, int out_size)
{
    const float* x  = (const float*)d_in[0];
    const float* sp = (const float*)d_in[1];
    const float* ed = (const float*)d_in[2];
    const unsigned char* mk = (const unsigned char*)d_in[3];
    const float* Wq = (const float*)d_in[4];
    const float* bq = (const float*)d_in[5];
    const float* Wk = (const float*)d_in[6];
    const float* bk = (const float*)d_in[7];
    const float* Wv = (const float*)d_in[8];
    const float* bv = (const float*)d_in[9];
    const float* Wo = (const float*)d_in[10];
    const float* bo = (const float*)d_in[11];
    float* out = (float*)d_out;

    dim3 gq(MROWS/128, HID/128, 3);     // 64 x 6 x 3
    qkv_kernel<<<gq, 256>>>(x, Wq, bq, Wk, bk, Wv, bv);

    dim3 ga(SQ/128, NB*NH);             // 8 x 96
    attn_kernel<<<ga, 256>>>(sp, ed, mk);

    dim3 go(MROWS/128, HID/128);        // 64 x 6
    oproj_kernel<<<go, 256>>>(Wo, bo, out);
}

// round 7
// speedup vs baseline: 6.5878x; 1.5012x over previous
#include <cuda_runtime.h>
#include <cuda_bf16.h>
#include <stdint.h>

#define NH   12
#define SQ   1024
#define NB   8
#define HID  768
#define MROWS (NB*SQ)   // 8192
#define LDT  40         // GEMM: padded bf16 row stride
#define ALD  72         // attention K/V tiles: 64 d-cols + 8 pad

// Scratch (allocation-free rule: device globals)
__device__ float g_q[MROWS*HID];
__device__ float g_k[MROWS*HID];
__device__ float g_v[MROWS*HID];
__device__ float g_attn[MROWS*HID];
__device__ float g_bias[(size_t)NB*SQ*SQ];   // sp+ed fused, mask applied

// ---------------------------------------------------------------------------
// Tensor-core primitives
// ---------------------------------------------------------------------------
__device__ __forceinline__ void mma_bf16(float* d, const uint32_t* a, const uint32_t* b)
{
    asm volatile(
        "mma.sync.aligned.m16n8k16.row.col.f32.bf16.bf16.f32 "
        "{%0,%1,%2,%3},{%4,%5,%6,%7},{%8,%9},{%0,%1,%2,%3};"
        : "+f"(d[0]), "+f"(d[1]), "+f"(d[2]), "+f"(d[3])
        : "r"(a[0]), "r"(a[1]), "r"(a[2]), "r"(a[3]), "r"(b[0]), "r"(b[1]));
}
__device__ __forceinline__ void ldsm4(uint32_t* r, uint32_t addr)
{
    asm volatile("ldmatrix.sync.aligned.m8n8.x4.shared.b16 {%0,%1,%2,%3},[%4];"
                 : "=r"(r[0]), "=r"(r[1]), "=r"(r[2]), "=r"(r[3]) : "r"(addr));
}
__device__ __forceinline__ void ldsm2(uint32_t* r, uint32_t addr)
{
    asm volatile("ldmatrix.sync.aligned.m8n8.x2.shared.b16 {%0,%1},[%2];"
                 : "=r"(r[0]), "=r"(r[1]) : "r"(addr));
}
__device__ __forceinline__ void ldsm2t(uint32_t* r, uint32_t addr)
{
    asm volatile("ldmatrix.sync.aligned.m8n8.x2.trans.shared.b16 {%0,%1},[%2];"
                 : "=r"(r[0]), "=r"(r[1]) : "r"(addr));
}
__device__ __forceinline__ float fexp2(float x)
{
    float y;
    asm("ex2.approx.ftz.f32 %0, %1;" : "=f"(y) : "f"(x));
    return y;
}
#define LOG2E 1.4426950408889634f

// split x into hi (bf16) + lo (bf16 of residual)
__device__ __forceinline__ void split4(float4 v, __nv_bfloat162& h0, __nv_bfloat162& h1,
                                       __nv_bfloat162& l0, __nv_bfloat162& l1)
{
    __nv_bfloat16 hx = __float2bfloat16_rn(v.x);
    __nv_bfloat16 hy = __float2bfloat16_rn(v.y);
    __nv_bfloat16 hz = __float2bfloat16_rn(v.z);
    __nv_bfloat16 hw = __float2bfloat16_rn(v.w);
    h0 = __nv_bfloat162(hx, hy);
    h1 = __nv_bfloat162(hz, hw);
    l0 = __nv_bfloat162(__float2bfloat16_rn(v.x - __bfloat162float(hx)),
                        __float2bfloat16_rn(v.y - __bfloat162float(hy)));
    l1 = __nv_bfloat162(__float2bfloat16_rn(v.z - __bfloat162float(hz)),
                        __float2bfloat16_rn(v.w - __bfloat162float(hw)));
}
__device__ __forceinline__ void split2(float x, float y, uint32_t& hi, uint32_t& lo)
{
    __nv_bfloat16 hx = __float2bfloat16_rn(x);
    __nv_bfloat16 hy = __float2bfloat16_rn(y);
    __nv_bfloat162 h(hx, hy);
    __nv_bfloat162 l(__float2bfloat16_rn(x - __bfloat162float(hx)),
                     __float2bfloat16_rn(y - __bfloat162float(hy)));
    hi = *(uint32_t*)&h;
    lo = *(uint32_t*)&l;
}

// ---------------------------------------------------------------------------
// Fused bias precompute: g_bias = sp + ed, mask -> -1e30
// ---------------------------------------------------------------------------
__global__ void __launch_bounds__(256) bias_kernel(const float* __restrict__ sp,
                                                   const float* __restrict__ ed,
                                                   const unsigned char* __restrict__ mk)
{
    const size_t i = (size_t)blockIdx.x * 256 + threadIdx.x;   // float4 index
    float4 s = ((const float4*)sp)[i];
    float4 e = ((const float4*)ed)[i];
    uint32_t m = ((const uint32_t*)mk)[i];
    float4 o;
    o.x = (m & 0x000000ffu) ? -1e30f : s.x + e.x;
    o.y = (m & 0x0000ff00u) ? -1e30f : s.y + e.y;
    o.z = (m & 0x00ff0000u) ? -1e30f : s.z + e.z;
    o.w = (m & 0xff000000u) ? -1e30f : s.w + e.w;
    ((float4*)g_bias)[i] = o;
}

// ---------------------------------------------------------------------------
// bf16-split tensor-core GEMM (validated; unchanged)
// ---------------------------------------------------------------------------
__device__ void gemm_mma(const float* __restrict__ X, const float* __restrict__ W,
                         const float* __restrict__ bias, float* __restrict__ out)
{
    __shared__ __align__(16) __nv_bfloat16 sAhi[128*LDT];
    __shared__ __align__(16) __nv_bfloat16 sAlo[128*LDT];
    __shared__ __align__(16) __nv_bfloat16 sBhi[128*LDT];
    __shared__ __align__(16) __nv_bfloat16 sBlo[128*LDT];

    const int tid  = threadIdx.x;
    const int lane = tid & 31;
    const int wid  = tid >> 5;
    const int wm   = (wid >> 2) * 64;
    const int wn   = (wid & 3) * 32;
    const int m0   = blockIdx.x * 128;
    const int n0   = blockIdx.y * 128;

    const int lrow = tid >> 3;
    const int lch  = (tid & 7) * 4;

    float acc[4][4][4];
#pragma unroll
    for (int mt = 0; mt < 4; mt++)
#pragma unroll
        for (int nt = 0; nt < 4; nt++)
#pragma unroll
            for (int r = 0; r < 4; r++) acc[mt][nt][r] = 0.f;

    const uint32_t aHi = (uint32_t)__cvta_generic_to_shared(sAhi);
    const uint32_t aLo = (uint32_t)__cvta_generic_to_shared(sAlo);
    const uint32_t bHi = (uint32_t)__cvta_generic_to_shared(sBhi);
    const uint32_t bLo = (uint32_t)__cvta_generic_to_shared(sBlo);
    const uint32_t aOff = ((wm + (lane & 15)) * LDT + (lane >> 4) * 8) * 2;
    const uint32_t bOff = ((wn + (lane & 7)) * LDT + ((lane >> 3) & 1) * 8) * 2;

    const float* Xp = X + (size_t)(m0 + lrow) * HID + lch;
    const float* Wp = W + (size_t)(n0 + lrow) * HID + lch;

    float4 pa[4], pb[4];
#pragma unroll
    for (int i = 0; i < 4; i++) {
        pa[i] = *(const float4*)(Xp + (size_t)i * 32 * HID);
        pb[i] = *(const float4*)(Wp + (size_t)i * 32 * HID);
    }

    for (int k0 = 0; k0 < HID; k0 += 32) {
#pragma unroll
        for (int i = 0; i < 4; i++) {
            int e = (lrow + 32 * i) * LDT + lch;
            __nv_bfloat162 h0, h1, l0, l1;
            split4(pa[i], h0, h1, l0, l1);
            *(__nv_bfloat162*)(sAhi + e)     = h0;
            *(__nv_bfloat162*)(sAhi + e + 2) = h1;
            *(__nv_bfloat162*)(sAlo + e)     = l0;
            *(__nv_bfloat162*)(sAlo + e + 2) = l1;
            split4(pb[i], h0, h1, l0, l1);
            *(__nv_bfloat162*)(sBhi + e)     = h0;
            *(__nv_bfloat162*)(sBhi + e + 2) = h1;
            *(__nv_bfloat162*)(sBlo + e)     = l0;
            *(__nv_bfloat162*)(sBlo + e + 2) = l1;
        }
        __syncthreads();

        if (k0 + 32 < HID) {
#pragma unroll
            for (int i = 0; i < 4; i++) {
                pa[i] = *(const float4*)(Xp + k0 + 32 + (size_t)i * 32 * HID);
                pb[i] = *(const float4*)(Wp + k0 + 32 + (size_t)i * 32 * HID);
            }
        }

#pragma unroll
        for (int ks = 0; ks < 32; ks += 16) {
            uint32_t ah[4][4], al[4][4];
#pragma unroll
            for (int mt = 0; mt < 4; mt++) {
                uint32_t off = aOff + (uint32_t)(mt * 16 * LDT + ks) * 2;
                ldsm4(ah[mt], aHi + off);
                ldsm4(al[mt], aLo + off);
            }
#pragma unroll
            for (int nt = 0; nt < 4; nt++) {
                uint32_t off = bOff + (uint32_t)(nt * 8 * LDT + ks) * 2;
                uint32_t bh[2], bl[2];
                ldsm2(bh, bHi + off);
                ldsm2(bl, bLo + off);
#pragma unroll
                for (int mt = 0; mt < 4; mt++) {
                    mma_bf16(acc[mt][nt], ah[mt], bh);
                    mma_bf16(acc[mt][nt], al[mt], bh);
                    mma_bf16(acc[mt][nt], ah[mt], bl);
                }
            }
        }
        __syncthreads();
    }

    const int g = lane >> 2;
    const int t = (lane & 3) * 2;
#pragma unroll
    for (int nt = 0; nt < 4; nt++) {
        const int nc = n0 + wn + nt * 8 + t;
        float2 bb = *(const float2*)(bias + nc);
#pragma unroll
        for (int mt = 0; mt < 4; mt++) {
            const int mr = m0 + wm + mt * 16 + g;
            float2 o0 = make_float2(acc[mt][nt][0] + bb.x, acc[mt][nt][1] + bb.y);
            float2 o1 = make_float2(acc[mt][nt][2] + bb.x, acc[mt][nt][3] + bb.y);
            *(float2*)(out + (size_t)mr * HID + nc)       = o0;
            *(float2*)(out + (size_t)(mr + 8) * HID + nc) = o1;
        }
    }
}

__global__ void __launch_bounds__(256) qkv_kernel(const float* __restrict__ X,
    const float* __restrict__ Wq, const float* __restrict__ bq,
    const float* __restrict__ Wk, const float* __restrict__ bk,
    const float* __restrict__ Wv, const float* __restrict__ bv)
{
    const float* W; const float* b; float* out;
    if (blockIdx.z == 0)      { W = Wq; b = bq; out = g_q; }
    else if (blockIdx.z == 1) { W = Wk; b = bk; out = g_k; }
    else                      { W = Wv; b = bv; out = g_v; }
    gemm_mma(X, W, b, out);
}

__global__ void __launch_bounds__(256) oproj_kernel(const float* __restrict__ Wo,
                                                    const float* __restrict__ bo,
                                                    float* __restrict__ out)
{
    gemm_mma(g_attn, Wo, bo, out);
}

// ---------------------------------------------------------------------------
// Tensor-core flash attention, v3 (fixed: g_bias referenced directly in
// device code — passing a __device__ global as a host-side kernel arg gave
// the host shadow address, silently read via ATS as garbage).
// CTA: 128 q-rows x one (b,h); 8 warps x 16 q-rows. Key tiles of 32,
// launch_bounds(256,2) -> 2 CTAs/SM. exp via MUFU ex2.approx.
// ---------------------------------------------------------------------------
__global__ void __launch_bounds__(256, 2) attn_kernel()
{
    __shared__ __align__(16) __nv_bfloat16 sKh[32*ALD];
    __shared__ __align__(16) __nv_bfloat16 sKl[32*ALD];
    __shared__ __align__(16) __nv_bfloat16 sVh[32*ALD];
    __shared__ __align__(16) __nv_bfloat16 sVl[32*ALD];

    const float* __restrict__ bias = g_bias;

    const int tid  = threadIdx.x;
    const int lane = tid & 31;
    const int w    = tid >> 5;
    const int g    = lane >> 2;        // 0..7
    const int t    = lane & 3;         // 0..3
    const int b    = blockIdx.y / NH;
    const int h    = blockIdx.y % NH;
    const int q0   = blockIdx.x * 128;

    const uint32_t kHb = (uint32_t)__cvta_generic_to_shared(sKh);
    const uint32_t kLb = (uint32_t)__cvta_generic_to_shared(sKl);
    const uint32_t vHb = (uint32_t)__cvta_generic_to_shared(sVh);
    const uint32_t vLb = (uint32_t)__cvta_generic_to_shared(sVl);

    const int qrow0 = q0 + w*16 + g;

    // ---- Q fragments direct from gmem (scaled by 1/8), split hi/lo ----
    uint32_t qh[4][4], ql[4][4];
    {
        const float* rowA = g_q + ((size_t)(b*SQ + qrow0))*HID + h*64;
        const float* rowB = rowA + (size_t)8*HID;
#pragma unroll
        for (int ks = 0; ks < 4; ks++) {
            const int c = ks*16 + t*2;
            float2 v;
            v = *(const float2*)(rowA + c);
            split2(v.x*0.125f, v.y*0.125f, qh[ks][0], ql[ks][0]);
            v = *(const float2*)(rowB + c);
            split2(v.x*0.125f, v.y*0.125f, qh[ks][1], ql[ks][1]);
            v = *(const float2*)(rowA + c + 8);
            split2(v.x*0.125f, v.y*0.125f, qh[ks][2], ql[ks][2]);
            v = *(const float2*)(rowB + c + 8);
            split2(v.x*0.125f, v.y*0.125f, qh[ks][3], ql[ks][3]);
        }
    }

    float m_i[2] = {-1e30f, -1e30f};
    float l_i[2] = {0.f, 0.f};
    float oacc[8][4];
#pragma unroll
    for (int nt = 0; nt < 8; nt++)
#pragma unroll
        for (int r = 0; r < 4; r++) oacc[nt][r] = 0.f;

    const size_t bias0 = ((size_t)b*SQ + qrow0) * SQ;
    const size_t bias1 = bias0 + 8*SQ;

    for (int kt = 0; kt < 32; kt++) {
        const int k0 = kt * 32;

        // ---- fused bias into score fragments (C init) ----
        float sv[4][4];
#pragma unroll
        for (int nt = 0; nt < 4; nt++) {
            const size_t c = k0 + nt*8 + t*2;
            float2 v0 = *(const float2*)(bias + bias0 + c);
            float2 v1 = *(const float2*)(bias + bias1 + c);
            sv[nt][0] = v0.x; sv[nt][1] = v0.y;
            sv[nt][2] = v1.x; sv[nt][3] = v1.y;
        }

        __syncthreads();   // previous iteration's K/V reads complete

        // ---- K, V tiles (32 rows) -> smem (split hi/lo) ----
        {
            const int lr = tid >> 3;            // 0..31
            const int d0 = (tid & 7) * 8;
            const float* kp = g_k + ((size_t)(b*SQ + k0 + lr))*HID + h*64 + d0;
            const float* vp = g_v + ((size_t)(b*SQ + k0 + lr))*HID + h*64 + d0;
            const int e = lr*ALD + d0;
#pragma unroll
            for (int i = 0; i < 2; i++) {
                __nv_bfloat162 h0, h1, l0, l1;
                split4(*(const float4*)(kp + i*4), h0, h1, l0, l1);
                *(__nv_bfloat162*)(sKh + e + i*4)     = h0;
                *(__nv_bfloat162*)(sKh + e + i*4 + 2) = h1;
                *(__nv_bfloat162*)(sKl + e + i*4)     = l0;
                *(__nv_bfloat162*)(sKl + e + i*4 + 2) = l1;
                split4(*(const float4*)(vp + i*4), h0, h1, l0, l1);
                *(__nv_bfloat162*)(sVh + e + i*4)     = h0;
                *(__nv_bfloat162*)(sVh + e + i*4 + 2) = h1;
                *(__nv_bfloat162*)(sVl + e + i*4)     = l0;
                *(__nv_bfloat162*)(sVl + e + i*4 + 2) = l1;
            }
        }
        __syncthreads();

        // ---- scores += Q.K^T (split: hh + lh + hl) ----
#pragma unroll
        for (int ks = 0; ks < 4; ks++) {
#pragma unroll
            for (int nt = 0; nt < 4; nt++) {
                const uint32_t boff = (uint32_t)((nt*8 + (lane & 7)) * ALD
                                     + ((lane >> 3) & 1) * 8 + ks*16) * 2;
                uint32_t kh[2], kl[2];
                ldsm2(kh, kHb + boff);
                ldsm2(kl, kLb + boff);
                mma_bf16(sv[nt], qh[ks], kh);
                mma_bf16(sv[nt], ql[ks], kh);
                mma_bf16(sv[nt], qh[ks], kl);
            }
        }

        // ---- online softmax (rows g and g+8; reduce over quad lanes) ----
        float mx0 = sv[0][0], mx1 = sv[0][2];
#pragma unroll
        for (int nt = 0; nt < 4; nt++) {
            mx0 = fmaxf(mx0, fmaxf(sv[nt][0], sv[nt][1]));
            mx1 = fmaxf(mx1, fmaxf(sv[nt][2], sv[nt][3]));
        }
        mx0 = fmaxf(mx0, __shfl_xor_sync(0xffffffffu, mx0, 1));
        mx0 = fmaxf(mx0, __shfl_xor_sync(0xffffffffu, mx0, 2));
        mx1 = fmaxf(mx1, __shfl_xor_sync(0xffffffffu, mx1, 1));
        mx1 = fmaxf(mx1, __shfl_xor_sync(0xffffffffu, mx1, 2));

        const float mn0 = fmaxf(m_i[0], mx0);
        const float mn1 = fmaxf(m_i[1], mx1);
        const float al0 = fexp2((m_i[0] - mn0) * LOG2E);
        const float al1 = fexp2((m_i[1] - mn1) * LOG2E);
        const float ml0 = mn0 * LOG2E;
        const float ml1 = mn1 * LOG2E;
        float ps0 = 0.f, ps1 = 0.f;
#pragma unroll
        for (int nt = 0; nt < 4; nt++) {
            sv[nt][0] = fexp2(fmaf(sv[nt][0], LOG2E, -ml0));
            sv[nt][1] = fexp2(fmaf(sv[nt][1], LOG2E, -ml0));
            sv[nt][2] = fexp2(fmaf(sv[nt][2], LOG2E, -ml1));
            sv[nt][3] = fexp2(fmaf(sv[nt][3], LOG2E, -ml1));
            ps0 += sv[nt][0] + sv[nt][1];
            ps1 += sv[nt][2] + sv[nt][3];
        }
        ps0 += __shfl_xor_sync(0xffffffffu, ps0, 1);
        ps0 += __shfl_xor_sync(0xffffffffu, ps0, 2);
        ps1 += __shfl_xor_sync(0xffffffffu, ps1, 1);
        ps1 += __shfl_xor_sync(0xffffffffu, ps1, 2);
        l_i[0] = l_i[0]*al0 + ps0;  m_i[0] = mn0;
        l_i[1] = l_i[1]*al1 + ps1;  m_i[1] = mn1;
#pragma unroll
        for (int nt = 0; nt < 8; nt++) {
            oacc[nt][0] *= al0; oacc[nt][1] *= al0;
            oacc[nt][2] *= al1; oacc[nt][3] *= al1;
        }

        // ---- PV: repack P per-ks, then MMA (V^T via ldmatrix.trans) ----
#pragma unroll
        for (int ks = 0; ks < 2; ks++) {
            uint32_t ph[4], pl[4];
            split2(sv[2*ks][0],   sv[2*ks][1],   ph[0], pl[0]);
            split2(sv[2*ks][2],   sv[2*ks][3],   ph[1], pl[1]);
            split2(sv[2*ks+1][0], sv[2*ks+1][1], ph[2], pl[2]);
            split2(sv[2*ks+1][2], sv[2*ks+1][3], ph[3], pl[3]);
#pragma unroll
            for (int nt = 0; nt < 8; nt++) {
                const uint32_t voff = (uint32_t)((ks*16 + (lane & 15)) * ALD + nt*8) * 2;
                uint32_t vh[2], vl[2];
                ldsm2t(vh, vHb + voff);
                ldsm2t(vl, vLb + voff);
                mma_bf16(oacc[nt], ph, vh);
                mma_bf16(oacc[nt], pl, vh);
                mma_bf16(oacc[nt], ph, vl);
            }
        }
    }

    // ---- normalize + write ----
    const float inv0 = 1.f / l_i[0];
    const float inv1 = 1.f / l_i[1];
    float* o0 = g_attn + ((size_t)(b*SQ + qrow0))*HID + h*64 + t*2;
    float* o1 = o0 + (size_t)8 * HID;
#pragma unroll
    for (int nt = 0; nt < 8; nt++) {
        *(float2*)(o0 + nt*8) = make_float2(oacc[nt][0]*inv0, oacc[nt][1]*inv0);
        *(float2*)(o1 + nt*8) = make_float2(oacc[nt][2]*inv1, oacc[nt][3]*inv1);
    }
}

// ---------------------------------------------------------------------------
extern "C" void kernel_launch(void* const* d_in, const int* in_sizes, int n_in,
                              void* d_out, int out_size)
{
    const float* x  = (const float*)d_in[0];
    const float* sp = (const float*)d_in[1];
    const float* ed = (const float*)d_in[2];
    const unsigned char* mk = (const unsigned char*)d_in[3];
    const float* Wq = (const float*)d_in[4];
    const float* bq = (const float*)d_in[5];
    const float* Wk = (const float*)d_in[6];
    const float* bk = (const float*)d_in[7];
    const float* Wv = (const float*)d_in[8];
    const float* bv = (const float*)d_in[9];
    const float* Wo = (const float*)d_in[10];
    const float* bo = (const float*)d_in[11];
    float* out = (float*)d_out;

    bias_kernel<<<(NB*SQ*SQ)/(256*4), 256>>>(sp, ed, mk);

    dim3 gq(MROWS/128, HID/128, 3);     // 64 x 6 x 3
    qkv_kernel<<<gq, 256>>>(x, Wq, bq, Wk, bk, Wv, bv);

    dim3 ga(SQ/128, NB*NH);             // 8 x 96
    attn_kernel<<<ga, 256>>>();

    dim3 go(MROWS/128, HID/128);        // 64 x 6
    oproj_kernel<<<go, 256>>>(Wo, bo, out);
}